// round 1
// baseline (speedup 1.0000x reference)
#include <cuda_runtime.h>
#include <math.h>

#define CC    96
#define HH    256
#define WWW   256
#define WS    16
#define NWIN  2048      // 8 * 16 * 16 windows
#define NREP  130       // representative positions per window under reflection
#define NREPP 144       // padded to 16*9 for clean register tiling

__device__ float g_ar[NWIN * CC];   // 1 + real_att per (window, channel)
__device__ float g_ai[CC];          // 1 + imag_att per channel (constant over windows)

// ---------------------------------------------------------------------------
// Kernel A: attention scalars.
// real pool per window = W_r @ (corner_pixel/16) + b_r  -> SE -> sigmoid
// imag pool = b_imag (constant)                          -> SE -> sigmoid
// ---------------------------------------------------------------------------
__global__ void attn_kernel(const float* __restrict__ x,
                            const float* __restrict__ w_real,
                            const float* __restrict__ b_real,
                            const float* __restrict__ b_imag,
                            const float* __restrict__ car_w1, const float* __restrict__ car_b1,
                            const float* __restrict__ car_w2, const float* __restrict__ car_b2,
                            const float* __restrict__ cai_w1, const float* __restrict__ cai_b1,
                            const float* __restrict__ cai_w2, const float* __restrict__ cai_b2)
{
    __shared__ float pool[CC];
    __shared__ float hid[32];
    __shared__ float cv[CC];
    int t = threadIdx.x;
    int win = blockIdx.x;

    if (win < NWIN) {
        int b  = win >> 8;
        int h0 = ((win >> 4) & 15) * WS;
        int w0 = (win & 15) * WS;
        if (t < CC) cv[t] = x[(((size_t)b * CC + t) * HH + h0) * WWW + w0];
        __syncthreads();
        if (t < CC) {
            float s = 0.f;
            #pragma unroll 4
            for (int k = 0; k < CC; k++) s += w_real[t * CC + k] * cv[k];
            pool[t] = s * (1.0f / 16.0f) + b_real[t];
        }
        __syncthreads();
        if (t < 32) {
            float s = car_b1[t];
            #pragma unroll 4
            for (int c = 0; c < CC; c++) s += car_w1[t * CC + c] * pool[c];
            hid[t] = fmaxf(s, 0.f);
        }
        __syncthreads();
        if (t < CC) {
            float s = car_b2[t];
            #pragma unroll
            for (int j = 0; j < 32; j++) s += car_w2[t * 32 + j] * hid[j];
            g_ar[win * CC + t] = 1.f + 1.f / (1.f + expf(-s));
        }
    } else {
        // constant imag attention: pool == b_imag exactly (mean of Im(FFT) of real signal = 0)
        if (t < CC) pool[t] = b_imag[t];
        __syncthreads();
        if (t < 32) {
            float s = cai_b1[t];
            #pragma unroll 4
            for (int c = 0; c < CC; c++) s += cai_w1[t * CC + c] * pool[c];
            hid[t] = fmaxf(s, 0.f);
        }
        __syncthreads();
        if (t < CC) {
            float s = cai_b2[t];
            #pragma unroll
            for (int j = 0; j < 32; j++) s += cai_w2[t * 32 + j] * hid[j];
            g_ai[t] = 1.f + 1.f / (1.f + expf(-s));
        }
    }
}

// ---------------------------------------------------------------------------
// Kernel B: main. Per window:
//   S[k][r] = (x[n] + x[rho(n)])/2   (even part at 130 representative positions)
//   D[k][r] = (x[n] - x[rho(n)])/2   (odd part)
//   E = W_r S ; O = W_i D            (two fused 96x130x96 fp32 GEMMs)
//   out[n]      = a_r*E + a_i*O  (+ 16*a_r*b_r at window origin)
//   out[rho(n)] = a_r*E - a_i*O
// ---------------------------------------------------------------------------
__global__ void __launch_bounds__(256, 1)
main_kernel(const float* __restrict__ x,
            const float* __restrict__ w_real,
            const float* __restrict__ w_imag,
            const float* __restrict__ b_real,
            float* __restrict__ out)
{
    extern __shared__ float sm[];
    float* Wr = sm;                    // 96*96
    float* Wi = Wr + CC * CC;          // 96*96
    float* S  = Wi + CC * CC;          // 96*144
    float* D  = S + CC * NREPP;        // 96*144

    int t   = threadIdx.x;
    int win = blockIdx.x;
    int b   = win >> 8;
    int h0  = ((win >> 4) & 15) * WS;
    int w0  = (win & 15) * WS;

    // load channel-mix matrices
    for (int idx = t; idx < CC * CC; idx += 256) {
        Wr[idx] = w_real[idx];
        Wi[idx] = w_imag[idx];
    }

    // build even/odd tiles
    const float* xb = x + (size_t)b * CC * HH * WWW;
    for (int idx = t; idx < CC * NREPP; idx += 256) {
        int k = idx / NREPP;
        int r = idx - k * NREPP;
        float sv = 0.f, dv = 0.f;
        if (r < NREP) {
            int p, q;
            if (r < 112) { p = 1 + (r >> 4); q = r & 15; }
            else { int r2 = r - 112; p = (r2 >= 9) ? 8 : 0; q = (r2 >= 9) ? (r2 - 9) : r2; }
            int p2 = (WS - p) & 15, q2 = (WS - q) & 15;
            float va = xb[((size_t)k * HH + h0 + p ) * WWW + w0 + q ];
            float vb = xb[((size_t)k * HH + h0 + p2) * WWW + w0 + q2];
            sv = 0.5f * (va + vb);
            dv = 0.5f * (va - vb);
        }
        S[k * NREPP + r] = sv;
        D[k * NREPP + r] = dv;
    }
    __syncthreads();

    // register-tiled fused dual GEMM: thread (i,j), i = t/16 -> 6 output channels,
    // j = t%16 -> 9 rep columns (stride 16)
    int i = t >> 4;
    int j = t & 15;

    float acc_e[6][9], acc_o[6][9];
    #pragma unroll
    for (int a = 0; a < 6; a++)
        #pragma unroll
        for (int m = 0; m < 9; m++) { acc_e[a][m] = 0.f; acc_o[a][m] = 0.f; }

    #pragma unroll 2
    for (int k = 0; k < CC; k++) {
        float wr[6], wi[6], sv[9], dv[9];
        #pragma unroll
        for (int a = 0; a < 6; a++) {
            wr[a] = Wr[(i + 16 * a) * CC + k];
            wi[a] = Wi[(i + 16 * a) * CC + k];
        }
        #pragma unroll
        for (int m = 0; m < 9; m++) {
            sv[m] = S[k * NREPP + j + 16 * m];
            dv[m] = D[k * NREPP + j + 16 * m];
        }
        #pragma unroll
        for (int a = 0; a < 6; a++)
            #pragma unroll
            for (int m = 0; m < 9; m++) {
                acc_e[a][m] += wr[a] * sv[m];
                acc_o[a][m] += wi[a] * dv[m];
            }
    }

    // epilogue: apply attention scalars, scatter to both halves of the window
    float arv[6], aiv[6];
    #pragma unroll
    for (int a = 0; a < 6; a++) {
        int c = i + 16 * a;
        arv[a] = g_ar[win * CC + c];
        aiv[a] = g_ai[c];
    }

    float* ob = out + (size_t)b * CC * HH * WWW;
    #pragma unroll
    for (int a = 0; a < 6; a++) {
        int c = i + 16 * a;
        float bias0 = 16.f * arv[a] * b_real[c];     // IFFT of constant bias -> origin only
        size_t base = ((size_t)c * HH + h0) * WWW + w0;
        #pragma unroll
        for (int m = 0; m < 9; m++) {
            int r = j + 16 * m;
            if (r >= NREP) continue;
            int p, q;
            if (r < 112) { p = 1 + m; q = j; }
            else { int r2 = r - 112; p = (r2 >= 9) ? 8 : 0; q = (r2 >= 9) ? (r2 - 9) : r2; }
            int p2 = (WS - p) & 15, q2 = (WS - q) & 15;
            float e = acc_e[a][m], o = acc_o[a][m];
            float v1 = arv[a] * e + aiv[a] * o;
            if (p == 0 && q == 0) v1 += bias0;
            ob[base + (size_t)p * WWW + q] = v1;
            if (p != p2 || q != q2)
                ob[base + (size_t)p2 * WWW + q2] = arv[a] * e - aiv[a] * o;
        }
    }
}

// ---------------------------------------------------------------------------
extern "C" void kernel_launch(void* const* d_in, const int* in_sizes, int n_in,
                              void* d_out, int out_size)
{
    const float* x      = (const float*)d_in[0];
    const float* w_real = (const float*)d_in[1];
    const float* b_real = (const float*)d_in[2];
    const float* w_imag = (const float*)d_in[3];
    const float* b_imag = (const float*)d_in[4];
    const float* car_w1 = (const float*)d_in[5];
    const float* car_b1 = (const float*)d_in[6];
    const float* car_w2 = (const float*)d_in[7];
    const float* car_b2 = (const float*)d_in[8];
    const float* cai_w1 = (const float*)d_in[9];
    const float* cai_b1 = (const float*)d_in[10];
    const float* cai_w2 = (const float*)d_in[11];
    const float* cai_b2 = (const float*)d_in[12];
    float* out = (float*)d_out;

    const int SMEM_BYTES = (2 * CC * CC + 2 * CC * NREPP) * (int)sizeof(float); // 184320
    cudaFuncSetAttribute(main_kernel, cudaFuncAttributeMaxDynamicSharedMemorySize, SMEM_BYTES);

    attn_kernel<<<NWIN + 1, 128>>>(x, w_real, b_real, b_imag,
                                   car_w1, car_b1, car_w2, car_b2,
                                   cai_w1, cai_b1, cai_w2, cai_b2);
    main_kernel<<<NWIN, 256, SMEM_BYTES>>>(x, w_real, w_imag, b_real, out);
}

// round 2
// speedup vs baseline: 1.4144x; 1.4144x over previous
#include <cuda_runtime.h>
#include <math.h>

#define CC    96
#define HH    256
#define WWW   256
#define WS    16
#define NWIN  2048      // 8 * 16 * 16 windows
#define NREP  130       // representative positions per window under reflection
#define NREPP 144       // padded to 16*9 for clean register tiling
#define WPITCH 97       // padded W row pitch (float2) to avoid bank conflicts

__device__ float g_ar[NWIN * CC];   // 1 + real_att per (window, channel)
__device__ float g_ai[CC];          // 1 + imag_att per channel (constant over windows)

// ---------------------------------------------------------------------------
// Kernel A: attention scalars (4-way split dot products to cut serial chains).
// ---------------------------------------------------------------------------
__global__ void __launch_bounds__(384)
attn_kernel(const float* __restrict__ x,
            const float* __restrict__ w_real,
            const float* __restrict__ b_real,
            const float* __restrict__ b_imag,
            const float* __restrict__ car_w1, const float* __restrict__ car_b1,
            const float* __restrict__ car_w2, const float* __restrict__ car_b2,
            const float* __restrict__ cai_w1, const float* __restrict__ cai_b1,
            const float* __restrict__ cai_w2, const float* __restrict__ cai_b2)
{
    __shared__ float cv[CC];
    __shared__ float part[CC][4];
    __shared__ float pool[CC];
    __shared__ float hpart[32][4];
    __shared__ float hid[32];
    int t = threadIdx.x;
    int win = blockIdx.x;
    bool is_real = (win < NWIN);

    if (is_real) {
        int b  = win >> 8;
        int h0 = ((win >> 4) & 15) * WS;
        int w0 = (win & 15) * WS;
        if (t < CC) cv[t] = x[(((size_t)b * CC + t) * HH + h0) * WWW + w0];
        __syncthreads();
        // pool = w_real @ cv / 16 + b_real   (4 threads per output)
        {
            int c = t >> 2, p = t & 3;
            const float* wrow = w_real + c * CC + p * 24;
            float s = 0.f;
            #pragma unroll
            for (int k = 0; k < 24; k++) s += wrow[k] * cv[p * 24 + k];
            part[c][p] = s;
        }
        __syncthreads();
        if (t < CC)
            pool[t] = (part[t][0] + part[t][1] + part[t][2] + part[t][3]) * (1.0f / 16.0f)
                      + b_real[t];
        __syncthreads();
    } else {
        if (t < CC) pool[t] = b_imag[t];
        __syncthreads();
    }

    const float* w1 = is_real ? car_w1 : cai_w1;
    const float* b1 = is_real ? car_b1 : cai_b1;
    const float* w2 = is_real ? car_w2 : cai_w2;
    const float* b2 = is_real ? car_b2 : cai_b2;

    if (t < 128) {
        int c = t >> 2, p = t & 3;
        const float* wrow = w1 + c * CC + p * 24;
        float s = 0.f;
        #pragma unroll
        for (int k = 0; k < 24; k++) s += wrow[k] * pool[p * 24 + k];
        hpart[c][p] = s;
    }
    __syncthreads();
    if (t < 32)
        hid[t] = fmaxf(hpart[t][0] + hpart[t][1] + hpart[t][2] + hpart[t][3] + b1[t], 0.f);
    __syncthreads();
    if (t < CC) {
        float s = b2[t];
        #pragma unroll
        for (int j = 0; j < 32; j++) s += w2[t * 32 + j] * hid[j];
        float a = 1.f + 1.f / (1.f + expf(-s));
        if (is_real) g_ar[win * CC + t] = a;
        else         g_ai[t] = a;
    }
}

// ---------------------------------------------------------------------------
// Kernel B: main. 512 threads, 1 window per CTA.
//   S[k][r] = (x[n]+x[rho(n)])/2 ; D[k][r] = (x[n]-x[rho(n)])/2   (interleaved)
//   E = W_r S ; O = W_i D  (fused dual GEMM, float2-interleaved operands)
//   out[n] = a_r*E + a_i*O (+16*a_r*b_r at origin) ; out[rho(n)] = a_r*E - a_i*O
// ---------------------------------------------------------------------------
__global__ void __launch_bounds__(512, 1)
main_kernel(const float* __restrict__ x,
            const float* __restrict__ w_real,
            const float* __restrict__ w_imag,
            const float* __restrict__ b_real,
            float* __restrict__ out)
{
    extern __shared__ float2 sm[];
    float2* W2 = sm;                    // [96][WPITCH]  (wr, wi)
    float2* SD = W2 + CC * WPITCH;      // [96][NREPP]   (s, d)

    int t   = threadIdx.x;
    int win = blockIdx.x;
    int b   = win >> 8;
    int h0  = ((win >> 4) & 15) * WS;
    int w0  = (win & 15) * WS;

    // load + interleave channel-mix matrices (coalesced global, conflict-free smem)
    for (int idx = t; idx < CC * CC; idx += 512) {
        int c = idx / CC, k = idx - c * CC;
        W2[c * WPITCH + k] = make_float2(w_real[idx], w_imag[idx]);
    }

    // build even/odd tile (interleaved)
    const float* xb = x + (size_t)b * CC * HH * WWW;
    for (int idx = t; idx < CC * NREPP; idx += 512) {
        int k = idx / NREPP;
        int r = idx - k * NREPP;
        float sv = 0.f, dv = 0.f;
        if (r < NREP) {
            int p, q;
            if (r < 112) { p = 1 + (r >> 4); q = r & 15; }
            else { int r2 = r - 112; p = (r2 >= 9) ? 8 : 0; q = (r2 >= 9) ? (r2 - 9) : r2; }
            int p2 = (WS - p) & 15, q2 = (WS - q) & 15;
            float va = xb[((size_t)k * HH + h0 + p ) * WWW + w0 + q ];
            float vb = xb[((size_t)k * HH + h0 + p2) * WWW + w0 + q2];
            sv = 0.5f * (va + vb);
            dv = 0.5f * (va - vb);
        }
        SD[k * NREPP + r] = make_float2(sv, dv);
    }
    __syncthreads();

    // register-tiled fused dual GEMM:
    //   j = t&15 -> 9 rep columns {j+16m}, i = t>>4 -> 3 channel rows {i, i+32, i+64}
    int j = t & 15;
    int i = t >> 4;

    float acc_e[3][9], acc_o[3][9];
    #pragma unroll
    for (int a = 0; a < 3; a++)
        #pragma unroll
        for (int m = 0; m < 9; m++) { acc_e[a][m] = 0.f; acc_o[a][m] = 0.f; }

    const float2* w0p = W2 + (i     ) * WPITCH;
    const float2* w1p = W2 + (i + 32) * WPITCH;
    const float2* w2p = W2 + (i + 64) * WPITCH;

    #pragma unroll 2
    for (int k = 0; k < CC; k++) {
        float2 w[3];
        w[0] = w0p[k]; w[1] = w1p[k]; w[2] = w2p[k];
        float2 sd[9];
        #pragma unroll
        for (int m = 0; m < 9; m++) sd[m] = SD[k * NREPP + j + 16 * m];
        #pragma unroll
        for (int a = 0; a < 3; a++)
            #pragma unroll
            for (int m = 0; m < 9; m++) {
                acc_e[a][m] += w[a].x * sd[m].x;
                acc_o[a][m] += w[a].y * sd[m].y;
            }
    }

    // epilogue: attention scalars + scatter to both halves (q-coalesced stores)
    float arv[3], aiv[3];
    #pragma unroll
    for (int a = 0; a < 3; a++) {
        int c = i + 32 * a;
        arv[a] = g_ar[win * CC + c];
        aiv[a] = g_ai[c];
    }

    float* ob = out + (size_t)b * CC * HH * WWW;
    #pragma unroll
    for (int a = 0; a < 3; a++) {
        int c = i + 32 * a;
        float bias0 = 16.f * arv[a] * b_real[c];
        size_t base = ((size_t)c * HH + h0) * WWW + w0;
        #pragma unroll
        for (int m = 0; m < 9; m++) {
            int r = j + 16 * m;
            if (r >= NREP) continue;
            int p, q;
            if (r < 112) { p = 1 + m; q = j; }
            else { int r2 = r - 112; p = (r2 >= 9) ? 8 : 0; q = (r2 >= 9) ? (r2 - 9) : r2; }
            int p2 = (WS - p) & 15, q2 = (WS - q) & 15;
            float e = acc_e[a][m], o = acc_o[a][m];
            float v1 = arv[a] * e + aiv[a] * o;
            if (p == 0 && q == 0) v1 += bias0;
            ob[base + (size_t)p * WWW + q] = v1;
            if (p != p2 || q != q2)
                ob[base + (size_t)p2 * WWW + q2] = arv[a] * e - aiv[a] * o;
        }
    }
}

// ---------------------------------------------------------------------------
extern "C" void kernel_launch(void* const* d_in, const int* in_sizes, int n_in,
                              void* d_out, int out_size)
{
    const float* x      = (const float*)d_in[0];
    const float* w_real = (const float*)d_in[1];
    const float* b_real = (const float*)d_in[2];
    const float* w_imag = (const float*)d_in[3];
    const float* b_imag = (const float*)d_in[4];
    const float* car_w1 = (const float*)d_in[5];
    const float* car_b1 = (const float*)d_in[6];
    const float* car_w2 = (const float*)d_in[7];
    const float* car_b2 = (const float*)d_in[8];
    const float* cai_w1 = (const float*)d_in[9];
    const float* cai_b1 = (const float*)d_in[10];
    const float* cai_w2 = (const float*)d_in[11];
    const float* cai_b2 = (const float*)d_in[12];
    float* out = (float*)d_out;

    const int SMEM_BYTES = (CC * WPITCH + CC * NREPP) * (int)sizeof(float2); // 185,088
    cudaFuncSetAttribute(main_kernel, cudaFuncAttributeMaxDynamicSharedMemorySize, SMEM_BYTES);

    attn_kernel<<<NWIN + 1, 384>>>(x, w_real, b_real, b_imag,
                                   car_w1, car_b1, car_w2, car_b2,
                                   cai_w1, cai_b1, cai_w2, cai_b2);
    main_kernel<<<NWIN, 512, SMEM_BYTES>>>(x, w_real, w_imag, b_real, out);
}